// round 5
// baseline (speedup 1.0000x reference)
#include <cuda_runtime.h>

// Problem constants
#define B_SZ   16
#define CIN    128
#define COUT   128
#define HD     512
#define HW     128      // input H = W
#define OHW    126      // output H = W (VALID conv, K=3)
#define REM    1152     // CIN * 9
#define WSIZE  147456   // COUT * REM

// Scratch (device globals: no allocation allowed in kernel_launch)
// g_w2 layout: [b][ci*9 + tap][co]  -> conv-friendly, contiguous per (b, ci)
__device__ float g_w2[B_SZ * REM * COUT];     // 9.4 MB
__device__ float g_bias[B_SZ * COUT];

// ---------------------------------------------------------------------------
// f32x2 packed-FP32 helpers (SASS FFMA2 path, PTX-only)
// ---------------------------------------------------------------------------
__device__ __forceinline__ void fma2(unsigned long long& d,
                                     unsigned long long a,
                                     unsigned long long b) {
    asm("fma.rn.f32x2 %0, %1, %2, %0;" : "+l"(d) : "l"(a), "l"(b));
}
__device__ __forceinline__ unsigned long long dup2(float v) {
    unsigned long long r;
    unsigned u = __float_as_uint(v);
    asm("mov.b64 %0, {%1, %1};" : "=l"(r) : "r"(u));
    return r;
}
__device__ __forceinline__ void unpack2(unsigned long long v, float& lo, float& hi) {
    asm("mov.b64 {%0, %1}, %2;" : "=f"(lo), "=f"(hi) : "l"(v));
}

// ---------------------------------------------------------------------------
// Kernel 1: hyper GEMM.  w[b,n] = sum_k h[b,k]*Wh[n,k] + bh[n]
// Output permuted: n = co*1152 + rem  ->  g_w2[(b*1152 + rem)*128 + co]
// grid = 144 blocks (WSIZE/1024, exactly one wave), 256 threads.
// Per-thread tile: 16 b (as 8 f32x2 pairs) x 4 n (strided by 256).
// ---------------------------------------------------------------------------
__global__ __launch_bounds__(256, 1)
void hyper_gemm_kernel(const float* __restrict__ Wh,
                       const float* __restrict__ h,
                       const float* __restrict__ bh) {
    extern __shared__ float smem[];
    float* sw = smem;               // [1024][33]  (stride 33: conflict-free)
    float* hs = smem + 1024 * 33;   // [32][16]    (kk-major so b-pairs are contiguous)

    const int t  = threadIdx.x;
    const int n0 = blockIdx.x * 1024;

    unsigned long long acc[32];     // [bb(8)][j(4)]
#pragma unroll
    for (int i = 0; i < 32; i++) acc[i] = 0ULL;

    for (int k0 = 0; k0 < HD; k0 += 32) {
        __syncthreads();
        // h fragment: hs[kk*16 + b] = h[b][k0+kk]   (tiny, L1-resident after tile 0)
#pragma unroll
        for (int q = 0; q < 2; q++) {
            int idx = t + q * 256;
            hs[idx] = h[(idx & 15) * HD + k0 + (idx >> 4)];
        }
        // Wh tile: 1024 rows x 32 k, coalesced float4 reads, de-interleaved into
        // stride-33 rows (store banks: (n + 4c + q) mod 32 all distinct -> no conflict)
#pragma unroll
        for (int r = 0; r < 32; r++) {
            int linear = r * 256 + t;
            int n = linear >> 3, c = linear & 7;
            float4 v = reinterpret_cast<const float4*>(Wh)
                           [(size_t)(n0 + n) * (HD / 4) + (k0 >> 2) + c];
            float* dst = sw + n * 33 + c * 4;
            dst[0] = v.x; dst[1] = v.y; dst[2] = v.z; dst[3] = v.w;
        }
        __syncthreads();

#pragma unroll
        for (int kk = 0; kk < 32; kk++) {
            unsigned long long hv[8];
            const unsigned long long* hp =
                reinterpret_cast<const unsigned long long*>(hs + kk * 16);
#pragma unroll
            for (int bb = 0; bb < 8; bb++) hv[bb] = hp[bb];   // LDS.64 broadcast

            unsigned long long wv[4];
#pragma unroll
            for (int j = 0; j < 4; j++)
                wv[j] = dup2(sw[(t + 256 * j) * 33 + kk]);    // bank = t mod 32: clean

#pragma unroll
            for (int bb = 0; bb < 8; bb++)
#pragma unroll
                for (int j = 0; j < 4; j++)
                    fma2(acc[bb * 4 + j], hv[bb], wv[j]);
        }
    }

    // Epilogue: add bh, scatter into conv-friendly layout
#pragma unroll
    for (int j = 0; j < 4; j++) {
        int n   = n0 + t + 256 * j;
        float bv = bh[n];
        int co  = n / REM;
        int rem = n - co * REM;
#pragma unroll
        for (int bb = 0; bb < 8; bb++) {
            float lo, hi;
            unpack2(acc[bb * 4 + j], lo, hi);
            g_w2[(size_t)((2 * bb)     * REM + rem) * COUT + co] = lo + bv;
            g_w2[(size_t)((2 * bb + 1) * REM + rem) * COUT + co] = hi + bv;
        }
    }
}

// ---------------------------------------------------------------------------
// Kernel 2: per-sample bias.  g_bias[b,co] = h[b]·Wb[co] + bb[co]
// warp per output; grid 256 x 256 threads covers 2048 outputs.
// ---------------------------------------------------------------------------
__global__ void hyper_bias_kernel(const float* __restrict__ h,
                                  const float* __restrict__ Wb,
                                  const float* __restrict__ bb) {
    int out  = blockIdx.x * 8 + (threadIdx.x >> 5);
    int lane = threadIdx.x & 31;
    int b  = out >> 7;
    int co = out & 127;
    float s = 0.f;
    for (int k = lane; k < HD; k += 32)
        s += h[b * HD + k] * Wb[co * HD + k];
#pragma unroll
    for (int o = 16; o > 0; o >>= 1) s += __shfl_xor_sync(0xffffffffu, s, o);
    if (lane == 0) g_bias[out] = s + bb[co];
}

// ---------------------------------------------------------------------------
// Kernel 3: batched direct conv (implicit GEMM over ci).
// Block = (oh, b). 256 threads = 16(tc: co-group) x 16(tw: ow base).
// Thread tile: 8 co (4 f32x2 pairs from smem) x 8 ow (strided by 16).
// Register-prefetch double buffering of per-ci x rows + weight slice.
// ---------------------------------------------------------------------------
__global__ __launch_bounds__(256, 2)
void hyper_conv_kernel(const float* __restrict__ x, float* __restrict__ y) {
    __shared__ float  xs[3 * 132];   // 3 input rows, cols 0..127 + zero pad 128..131
    __shared__ float4 ws4[288];      // w slice for current ci: [tap(9)][co(128)]
    float* ws = reinterpret_cast<float*>(ws4);

    const int t  = threadIdx.x;
    const int tc = t >> 4;           // 0..15 : co block (8 co each)
    const int tw = t & 15;           // 0..15 : ow base
    const int oh = blockIdx.x;       // 0..125
    const int b  = blockIdx.y;       // 0..15

    unsigned long long acc[32];      // [ii(4 co-pairs)][j(8 ow)]
#pragma unroll
    for (int i = 0; i < 32; i++) acc[i] = 0ULL;

    if (t < 12) xs[(t >> 2) * 132 + 128 + (t & 3)] = 0.f;   // pad once

    const float*  xbase = x + (size_t)b * CIN * HW * HW + (size_t)oh * HW;
    const float4* wbase = reinterpret_cast<const float4*>(g_w2 + (size_t)b * REM * COUT);

    // prefetch ci = 0
    float  xr0, xr1;
    float4 wr0, wr1;
    {
        int idx1 = t + 256;
        xr0 = xbase[(t >> 7) * HW + (t & 127)];
        xr1 = (idx1 < 384) ? xbase[(idx1 >> 7) * HW + (idx1 & 127)] : 0.f;
        wr0 = (t < 288) ? wbase[t] : make_float4(0.f, 0.f, 0.f, 0.f);
        wr1 = (t < 32)  ? wbase[t + 256] : make_float4(0.f, 0.f, 0.f, 0.f);
    }

    for (int ci = 0; ci < CIN; ci++) {
        __syncthreads();                       // prior tile's smem reads done
        // commit prefetched tile
        {
            int idx1 = t + 256;
            xs[(t >> 7) * 132 + (t & 127)] = xr0;
            if (idx1 < 384) xs[(idx1 >> 7) * 132 + (idx1 & 127)] = xr1;
            if (t < 288) ws4[t] = wr0;
            if (t < 32)  ws4[t + 256] = wr1;
        }
        // issue next tile's loads (latency hidden behind compute)
        if (ci + 1 < CIN) {
            const float* xp = xbase + (size_t)(ci + 1) * HW * HW;
            int idx1 = t + 256;
            xr0 = xp[(t >> 7) * HW + (t & 127)];
            if (idx1 < 384) xr1 = xp[(idx1 >> 7) * HW + (idx1 & 127)];
            const float4* wp = wbase + (size_t)(ci + 1) * 288;
            if (t < 288) wr0 = wp[t];
            if (t < 32)  wr1 = wp[t + 256];
        }
        __syncthreads();

#pragma unroll
        for (int kh = 0; kh < 3; kh++) {
#pragma unroll
            for (int kw = 0; kw < 3; kw++) {
                const unsigned long long* wp2 =
                    reinterpret_cast<const unsigned long long*>(
                        ws + (kh * 3 + kw) * COUT + tc * 8);
                unsigned long long wf[4];
#pragma unroll
                for (int ii = 0; ii < 4; ii++) wf[ii] = wp2[ii];  // co-pairs, free pack
#pragma unroll
                for (int j = 0; j < 8; j++) {
                    unsigned long long xd =
                        dup2(xs[kh * 132 + tw + j * 16 + kw]);    // conflict-free
#pragma unroll
                    for (int ii = 0; ii < 4; ii++)
                        fma2(acc[ii * 8 + j], wf[ii], xd);
                }
            }
        }
    }

    // Epilogue: + per-sample bias, guarded stores (ow < 126)
    const float* bp = g_bias + b * COUT;
#pragma unroll
    for (int ii = 0; ii < 4; ii++) {
        int co0 = tc * 8 + 2 * ii;
        float b0 = bp[co0], b1 = bp[co0 + 1];
        float* y0 = y + (((size_t)b * COUT + co0) * OHW + oh) * OHW;
        float* y1 = y0 + (size_t)OHW * OHW;
#pragma unroll
        for (int j = 0; j < 8; j++) {
            int ow = tw + j * 16;
            if (ow < OHW) {
                float lo, hi;
                unpack2(acc[ii * 8 + j], lo, hi);
                y0[ow] = lo + b0;
                y1[ow] = hi + b1;
            }
        }
    }
}

// ---------------------------------------------------------------------------
// Launch. Inputs (metadata order): x, h, Wh, bh, Wb, bb. Output: float32.
// Graph-capturable: kernel launches only; scratch lives in __device__ globals.
// ---------------------------------------------------------------------------
extern "C" void kernel_launch(void* const* d_in, const int* in_sizes, int n_in,
                              void* d_out, int out_size) {
    const float* x  = (const float*)d_in[0];
    const float* h  = (const float*)d_in[1];
    const float* Wh = (const float*)d_in[2];
    const float* bh = (const float*)d_in[3];
    const float* Wb = (const float*)d_in[4];
    const float* bb = (const float*)d_in[5];
    float* y = (float*)d_out;

    const int smem_bytes = (1024 * 33 + 32 * 16) * (int)sizeof(float);  // 137216
    cudaFuncSetAttribute(hyper_gemm_kernel,
                         cudaFuncAttributeMaxDynamicSharedMemorySize, smem_bytes);

    hyper_gemm_kernel<<<WSIZE / 1024, 256, smem_bytes>>>(Wh, h, bh);  // 144 blocks
    hyper_bias_kernel<<<(B_SZ * COUT) / 8, 256>>>(h, Wb, bb);         // 256 blocks
    hyper_conv_kernel<<<dim3(OHW, B_SZ), 256>>>(x, y);                // 126 x 16
}